// round 6
// baseline (speedup 1.0000x reference)
#include <cuda_runtime.h>
#include <cstdint>
#include <math_constants.h>

// ============================================================================
// KineticOptimalDiscreteEulerSolver — collapsed 2-sparse form (R6).
//
// out[n] row is zero except (when x1 != x_t):
//   out[x1] = +u, out[x_t] = -u,
//   u = max(p_t[xt]*pd[x1] - pd[xt]*p_t[x1], 0) / (p_t[x1] + EPS)
//
// x1 = jax.random.categorical(jax.random.key(1), logits), partitionable
// threefry stream (verified passing in R3/R5):
//   (o0,o1) = threefry2x32(key=(0,1), counter=(0, flat_idx)); bits = o0^o1
//   uniform = max(tiny, bitcast((bits>>9)|0x3f800000) - 1)
//   gumbel  = -log(-log(uniform)); argmax(logits+gumbel), first-index ties.
//
// R6 vs R5 (6.34us, 64 fat CTAs on 64/148 SMs): split each token into 4
// chunks of 256 -> 256 CTAs cover the chip; partial (argmax key, chunk sum)
// written to fixed __device__ scratch slots (all overwritten every run ->
// graph-deterministic, no reset); tiny kernel2 reduces 4 partials/token and
// writes the two sparse entries.
// ============================================================================

#define TINYF 1.17549435e-38f
#define EPSF  1e-8f
#define CHUNK 256
#define MAX_PARTS 65536   // supports N*CHUNKS up to 64K

__device__ unsigned long long g_part_key[MAX_PARTS];
__device__ float              g_part_sum[MAX_PARTS];

__device__ __forceinline__ uint32_t rotl32(uint32_t x, int r) {
    return (x << r) | (x >> (32 - r));
}

// Threefry-2x32, 20 rounds, key (0, 1)
__device__ __forceinline__ void threefry2x32_key01(uint32_t c0, uint32_t c1,
                                                   uint32_t& o0, uint32_t& o1) {
    const uint32_t ks0 = 0u;
    const uint32_t ks1 = 1u;
    const uint32_t ks2 = 0x1BD11BDAu ^ ks0 ^ ks1;  // 0x1BD11BDB
    uint32_t x0 = c0 + ks0;
    uint32_t x1 = c1 + ks1;

#define TF_ROUND(r) { x0 += x1; x1 = rotl32(x1, r); x1 ^= x0; }
#define TF_G0 TF_ROUND(13) TF_ROUND(15) TF_ROUND(26) TF_ROUND(6)
#define TF_G1 TF_ROUND(17) TF_ROUND(29) TF_ROUND(16) TF_ROUND(24)

    TF_G0  x0 += ks1; x1 += ks2 + 1u;
    TF_G1  x0 += ks2; x1 += ks0 + 2u;
    TF_G0  x0 += ks0; x1 += ks1 + 3u;
    TF_G1  x0 += ks1; x1 += ks2 + 4u;
    TF_G0  x0 += ks2; x1 += ks0 + 5u;

#undef TF_ROUND
#undef TF_G0
#undef TF_G1
    o0 = x0;
    o1 = x1;
}

// Inner log must be accurate-relative (u->1 => w->0); outer log only needs
// small absolute error => MUFU-based __logf.
__device__ __forceinline__ float jax_gumbel_part(uint32_t idx) {
    uint32_t o0, o1;
    threefry2x32_key01(0u, idx, o0, o1);
    uint32_t bits = o0 ^ o1;
    float f = __uint_as_float((bits >> 9) | 0x3f800000u) - 1.0f;
    float u = fmaxf(TINYF, f);
    float w = -logf(u);          // accurate (relative error matters)
    return -__logf(w);           // fast (absolute error ~2e-7 is harmless)
}

// Monotone float->uint32 mapping for unsigned compare (total order).
__device__ __forceinline__ uint32_t float_mono(float f) {
    uint32_t b = __float_as_uint(f);
    return (b & 0x80000000u) ? ~b : (b | 0x80000000u);
}

// ---------------------------------------------------------------------------
// Kernel 1: one CTA per (token, chunk). 256 threads, 1 element each.
// Zeroes its slice of the output row, computes the chunk's gumbel-argmax key
// and source_p chunk sum, writes them to fixed scratch slots.
// ---------------------------------------------------------------------------
__global__ void __launch_bounds__(CHUNK)
ke_partial_kernel(const float* __restrict__ logits,
                  const float* __restrict__ source_p,
                  float* __restrict__ out,
                  int V, int chunks) {
    const int part  = blockIdx.x;          // token * chunks + chunk
    const int n     = part / chunks;
    const int chunk = part - n * chunks;
    const int tid   = threadIdx.x;
    const int lane  = tid & 31;
    const int warp  = tid >> 5;

    __shared__ unsigned long long skey[8];
    __shared__ float ssum[8];

    const int v = chunk * CHUNK + tid;     // vocab index handled by this thread
    const uint32_t idx = (uint32_t)n * (uint32_t)V + (uint32_t)v;

    // Zero this thread's output element (harness poisons d_out).
    out[(size_t)n * V + v] = 0.f;

    // Per-element gumbel score + source_p value.
    float g = jax_gumbel_part(idx);
    float score = logits[idx] + g;
    unsigned long long key =
        ((unsigned long long)float_mono(score) << 32) |
        (unsigned long long)(~(uint32_t)v);
    float psum = source_p[v];

    // Warp reduction.
#pragma unroll
    for (int s = 16; s > 0; s >>= 1) {
        unsigned long long ok = __shfl_down_sync(0xffffffffu, key, s);
        float os = __shfl_down_sync(0xffffffffu, psum, s);
        if (ok > key) key = ok;
        psum += os;
    }
    if (lane == 0) { skey[warp] = key; ssum[warp] = psum; }
    __syncthreads();

    // Warp 0 reduces 8 partials and writes the CTA's scratch slot.
    if (warp == 0 && lane < 8) {
        key  = skey[lane];
        psum = ssum[lane];
#pragma unroll
        for (int s = 4; s > 0; s >>= 1) {
            unsigned long long ok = __shfl_down_sync(0x000000ffu, key, s);
            float os = __shfl_down_sync(0x000000ffu, psum, s);
            if (ok > key) key = ok;
            psum += os;
        }
        if (lane == 0) {
            g_part_key[part] = key;
            g_part_sum[part] = psum;
        }
    }
}

// ---------------------------------------------------------------------------
// Kernel 2: one thread per token. Reduces `chunks` partials, computes the
// two-entry result, writes it (output already zeroed by kernel 1).
// ---------------------------------------------------------------------------
__global__ void ke_final_kernel(const float* __restrict__ source_p,
                                const int*   __restrict__ x_t,
                                const float* __restrict__ t_arr,
                                float* __restrict__ out,
                                int V, int chunks, int N) {
    const int n = blockIdx.x * blockDim.x + threadIdx.x;
    if (n >= N) return;

    unsigned long long key = 0ull;
    float S = 0.f;
    const int base = n * chunks;
    for (int c = 0; c < chunks; c++) {
        unsigned long long k = g_part_key[base + c];
        if (k > key) key = k;
        S += g_part_sum[base + c];
    }

    int x1 = (int)(~(uint32_t)(key & 0xffffffffull));
    int xt = x_t[n];
    if (x1 != xt) {
        float t    = t_arr[0];
        float omt  = 1.0f - t;
        float spx1 = source_p[x1] / S;
        float spxt = source_p[xt] / S;
        float pt_xt = omt * spxt;          // p_t[xt]
        float pt_x1 = omt * spx1 + t;      // p_t[x1]
        float pd_x1 = 1.0f - spx1;         // p_t_dot[x1]
        float pd_xt = -spxt;               // p_t_dot[xt]
        float j  = fmaxf(pt_xt * pd_x1 - pd_xt * pt_x1, 0.0f);
        float u  = j / (pt_x1 + EPSF);
        float* orow = out + (size_t)n * V;
        orow[x1] =  u;
        orow[xt] = -u;
    }
    // x1 == xt: row stays identically zero.
}

// ---------------------------------------------------------------------------
// Fallback: monolithic single-kernel path (R5, passing) for shapes where the
// chunked path doesn't apply.
// ---------------------------------------------------------------------------
__global__ void __launch_bounds__(1024, 1)
kinetic_euler_mono(const float* __restrict__ logits,
                   const float* __restrict__ source_p,
                   const int*   __restrict__ x_t,
                   const float* __restrict__ t_arr,
                   float* __restrict__ out,
                   int V) {
    const int n   = blockIdx.x;
    const int tid = threadIdx.x;
    const int nthreads = blockDim.x;
    const int lane = tid & 31;
    const int warp = tid >> 5;

    __shared__ unsigned long long skey[32];
    __shared__ float ssum[32];
    if (tid < 32) { skey[tid] = 0ull; ssum[tid] = 0.f; }

    const float* lrow = logits + (size_t)n * V;
    float* orow = out + (size_t)n * V;

    int   xt_pre = 0;
    float t_pre  = 0.f;
    if (tid == 0) { xt_pre = x_t[n]; t_pre = t_arr[0]; }

    for (int v = tid; v < V; v += nthreads)
        orow[v] = 0.f;

    unsigned long long key = 0ull;
    float psum = 0.f;
    for (int v = tid; v < V; v += nthreads) {
        float g = jax_gumbel_part((uint32_t)n * (uint32_t)V + (uint32_t)v);
        float score = lrow[v] + g;
        unsigned long long k =
            ((unsigned long long)float_mono(score) << 32) |
            (unsigned long long)(~(uint32_t)v);
        if (k > key) key = k;
        psum += source_p[v];
    }
#pragma unroll
    for (int s = 16; s > 0; s >>= 1) {
        unsigned long long ok = __shfl_down_sync(0xffffffffu, key, s);
        float os = __shfl_down_sync(0xffffffffu, psum, s);
        if (ok > key) key = ok;
        psum += os;
    }
    if (lane == 0) { skey[warp] = key; ssum[warp] = psum; }
    __syncthreads();

    if (warp == 0) {
        key  = skey[lane];
        psum = ssum[lane];
#pragma unroll
        for (int s = 16; s > 0; s >>= 1) {
            unsigned long long ok = __shfl_down_sync(0xffffffffu, key, s);
            float os = __shfl_down_sync(0xffffffffu, psum, s);
            if (ok > key) key = ok;
            psum += os;
        }
        if (lane == 0) {
            int   x1 = (int)(~(uint32_t)(key & 0xffffffffull));
            float S  = psum;
            int   xt = xt_pre;
            if (x1 != xt) {
                float t    = t_pre;
                float omt  = 1.0f - t;
                float spx1 = source_p[x1] / S;
                float spxt = source_p[xt] / S;
                float pt_xt = omt * spxt;
                float pt_x1 = omt * spx1 + t;
                float pd_x1 = 1.0f - spx1;
                float pd_xt = -spxt;
                float j  = fmaxf(pt_xt * pd_x1 - pd_xt * pt_x1, 0.0f);
                float u  = j / (pt_x1 + EPSF);
                orow[x1] =  u;
                orow[xt] = -u;
            }
        }
    }
}

extern "C" void kernel_launch(void* const* d_in, const int* in_sizes, int n_in,
                              void* d_out, int out_size) {
    // Bind inputs by element count (sizes distinct: N*V > V > N > 1).
    int li = 0, spi = 1, xti = 2, ti = 3;
    if (n_in == 4) {
        int order[4] = {0, 1, 2, 3};
        for (int a = 0; a < 4; a++)
            for (int b = a + 1; b < 4; b++)
                if (in_sizes[order[b]] > in_sizes[order[a]]) {
                    int tmp = order[a]; order[a] = order[b]; order[b] = tmp;
                }
        li  = order[0];   // N*V
        spi = order[1];   // V
        xti = order[2];   // N
        ti  = order[3];   // 1
    }

    const float* logits   = (const float*)d_in[li];
    const float* source_p = (const float*)d_in[spi];
    const int*   x_t      = (const int*)d_in[xti];
    const float* t_arr    = (const float*)d_in[ti];
    float* out = (float*)d_out;

    int total = in_sizes[li];     // N * V
    int V     = in_sizes[spi];    // vocab size
    int N     = total / V;        // tokens

    if ((V % CHUNK) == 0 && (size_t)N * (V / CHUNK) <= MAX_PARTS) {
        int chunks = V / CHUNK;
        ke_partial_kernel<<<N * chunks, CHUNK>>>(logits, source_p, out, V, chunks);
        int fb = 128;
        ke_final_kernel<<<(N + fb - 1) / fb, fb>>>(source_p, x_t, t_arr, out,
                                                   V, chunks, N);
    } else {
        int threads = (V >= 1024) ? 1024 : ((V + 31) & ~31);
        if (threads < 32) threads = 32;
        kinetic_euler_mono<<<N, threads>>>(logits, source_p, x_t, t_arr, out, V);
    }
}

// round 7
// speedup vs baseline: 1.2935x; 1.2935x over previous
#include <cuda_runtime.h>
#include <cooperative_groups.h>
#include <cstdint>
#include <math_constants.h>

namespace cg = cooperative_groups;

// ============================================================================
// KineticOptimalDiscreteEulerSolver — collapsed 2-sparse form (R7).
//
// out[n] row is zero except (when x1 != x_t):
//   out[x1] = +u, out[x_t] = -u,
//   u = max(p_t[xt]*pd[x1] - pd[xt]*p_t[x1], 0) / (p_t[x1] + EPS)
//
// x1 = jax.random.categorical(jax.random.key(1), logits), partitionable
// threefry stream (verified in R3/R5/R6):
//   (o0,o1) = threefry2x32(key=(0,1), counter=(0, flat_idx)); bits = o0^o1
//   uniform = max(tiny, bitcast((bits>>9)|0x3f800000) - 1)
//   gumbel  = -log(-log(uniform)); argmax(logits+gumbel), first-index ties.
//
// R7 vs R5 (6.34us, 64 fat CTAs on 64 SMs) and R6 (8.32us, 2-kernel split
// killed by cold-cache serial tail): SINGLE kernel, 2-CTA cluster per token
// -> 128 CTAs x 512 threads cover 128/148 SMs; rank1 ships its (key, sum)
// partial to rank0 via DSMEM; cluster.sync() orders everything; rank0 writes
// the two sparse entries with source_p L1-warm.
// ============================================================================

#define TINYF 1.17549435e-38f
#define EPSF  1e-8f

__device__ __forceinline__ uint32_t rotl32(uint32_t x, int r) {
    return (x << r) | (x >> (32 - r));
}

// Threefry-2x32, 20 rounds, key (0, 1)
__device__ __forceinline__ void threefry2x32_key01(uint32_t c0, uint32_t c1,
                                                   uint32_t& o0, uint32_t& o1) {
    const uint32_t ks0 = 0u;
    const uint32_t ks1 = 1u;
    const uint32_t ks2 = 0x1BD11BDAu ^ ks0 ^ ks1;  // 0x1BD11BDB
    uint32_t x0 = c0 + ks0;
    uint32_t x1 = c1 + ks1;

#define TF_ROUND(r) { x0 += x1; x1 = rotl32(x1, r); x1 ^= x0; }
#define TF_G0 TF_ROUND(13) TF_ROUND(15) TF_ROUND(26) TF_ROUND(6)
#define TF_G1 TF_ROUND(17) TF_ROUND(29) TF_ROUND(16) TF_ROUND(24)

    TF_G0  x0 += ks1; x1 += ks2 + 1u;
    TF_G1  x0 += ks2; x1 += ks0 + 2u;
    TF_G0  x0 += ks0; x1 += ks1 + 3u;
    TF_G1  x0 += ks1; x1 += ks2 + 4u;
    TF_G0  x0 += ks2; x1 += ks0 + 5u;

#undef TF_ROUND
#undef TF_G0
#undef TF_G1
    o0 = x0;
    o1 = x1;
}

// Inner log must be accurate-relative (u->1 => w->0); outer log only needs
// small absolute error => MUFU-based __logf.
__device__ __forceinline__ float jax_gumbel_part(uint32_t idx) {
    uint32_t o0, o1;
    threefry2x32_key01(0u, idx, o0, o1);
    uint32_t bits = o0 ^ o1;
    float f = __uint_as_float((bits >> 9) | 0x3f800000u) - 1.0f;
    float u = fmaxf(TINYF, f);
    float w = -logf(u);          // accurate (relative error matters)
    return -__logf(w);           // fast (absolute error ~2e-7 is harmless)
}

// Monotone float->uint32 mapping for unsigned compare (total order).
__device__ __forceinline__ uint32_t float_mono(float f) {
    uint32_t b = __float_as_uint(f);
    return (b & 0x80000000u) ? ~b : (b | 0x80000000u);
}

// Shared tail math: compute and write the two sparse entries.
__device__ __forceinline__ void write_sparse_pair(float* orow,
                                                  const float* __restrict__ source_p,
                                                  int x1, int xt, float t, float S) {
    if (x1 != xt) {
        float omt  = 1.0f - t;
        float spx1 = source_p[x1] / S;
        float spxt = source_p[xt] / S;
        float pt_xt = omt * spxt;          // p_t[xt]
        float pt_x1 = omt * spx1 + t;      // p_t[x1]
        float pd_x1 = 1.0f - spx1;         // p_t_dot[x1]
        float pd_xt = -spxt;               // p_t_dot[xt]
        float j  = fmaxf(pt_xt * pd_x1 - pd_xt * pt_x1, 0.0f);
        float u  = j / (pt_x1 + EPSF);
        orow[x1] =  u;
        orow[xt] = -u;
    }
    // x1 == xt: row stays identically zero.
}

// ---------------------------------------------------------------------------
// Cluster kernel: 2 CTAs per token, 512 threads each, 1 vocab element/thread.
// ---------------------------------------------------------------------------
__global__ void __launch_bounds__(512, 1) __cluster_dims__(2, 1, 1)
ke_cluster_kernel(const float* __restrict__ logits,
                  const float* __restrict__ source_p,
                  const int*   __restrict__ x_t,
                  const float* __restrict__ t_arr,
                  float* __restrict__ out,
                  int V) {
    cg::cluster_group cluster = cg::this_cluster();
    const uint32_t rank = cluster.block_rank();      // 0 or 1
    const int n   = blockIdx.x >> 1;                 // token index
    const int tid = threadIdx.x;
    const int lane = tid & 31;
    const int warp = tid >> 5;                       // 0..15
    const int halfV = V >> 1;                        // 512

    __shared__ unsigned long long skey[16];
    __shared__ float ssum[16];
    __shared__ unsigned long long peer_key;          // written by rank 1 (in rank 0)
    __shared__ float peer_sum;

    const int v = (int)rank * halfV + tid;           // vocab index of this thread
    const uint32_t idx = (uint32_t)n * (uint32_t)V + (uint32_t)v;
    float* orow = out + (size_t)n * V;

    // Prefetch tail operands early (rank 0 only uses them).
    int   xt_pre = 0;
    float t_pre  = 0.f;
    if (rank == 0 && tid == 0) { xt_pre = x_t[n]; t_pre = t_arr[0]; }

    // Zero this thread's output element (harness poisons d_out).
    orow[v] = 0.f;

    // Per-element gumbel score + source_p value.
    float g = jax_gumbel_part(idx);
    float score = logits[idx] + g;
    unsigned long long key =
        ((unsigned long long)float_mono(score) << 32) |
        (unsigned long long)(~(uint32_t)v);
    float psum = source_p[v];

    // Warp reduction.
#pragma unroll
    for (int s = 16; s > 0; s >>= 1) {
        unsigned long long ok = __shfl_down_sync(0xffffffffu, key, s);
        float os = __shfl_down_sync(0xffffffffu, psum, s);
        if (ok > key) key = ok;
        psum += os;
    }
    if (lane == 0) { skey[warp] = key; ssum[warp] = psum; }
    __syncthreads();

    // Warp 0 reduces the 16 per-warp partials.
    if (warp == 0) {
        if (lane < 16) { key = skey[lane]; psum = ssum[lane]; }
        else           { key = 0ull;       psum = 0.f; }
#pragma unroll
        for (int s = 8; s > 0; s >>= 1) {
            unsigned long long ok = __shfl_down_sync(0x0000ffffu, key, s);
            float os = __shfl_down_sync(0x0000ffffu, psum, s);
            if (ok > key) key = ok;
            psum += os;
        }
        // Rank 1 ships its partial into rank 0's SMEM (DSMEM store).
        if (rank == 1 && lane == 0) {
            unsigned long long* dk =
                (unsigned long long*)cluster.map_shared_rank(&peer_key, 0);
            float* ds = (float*)cluster.map_shared_rank(&peer_sum, 0);
            *dk = key;
            *ds = psum;
        }
    }

    // Orders: rank1's DSMEM partial AND rank1's output-zero stores before
    // rank0's reads/final writes (release on arrive, acquire on wait).
    cluster.sync();

    if (rank == 0 && warp == 0 && lane == 0) {
        unsigned long long ok = peer_key;
        float S = psum + peer_sum;
        if (ok > key) key = ok;
        int x1 = (int)(~(uint32_t)(key & 0xffffffffull));
        write_sparse_pair(orow, source_p, x1, xt_pre, t_pre, S);
    }
}

// ---------------------------------------------------------------------------
// Fallback: monolithic single-kernel path (R5, passing) for odd shapes.
// ---------------------------------------------------------------------------
__global__ void __launch_bounds__(1024, 1)
kinetic_euler_mono(const float* __restrict__ logits,
                   const float* __restrict__ source_p,
                   const int*   __restrict__ x_t,
                   const float* __restrict__ t_arr,
                   float* __restrict__ out,
                   int V) {
    const int n   = blockIdx.x;
    const int tid = threadIdx.x;
    const int nthreads = blockDim.x;
    const int lane = tid & 31;
    const int warp = tid >> 5;

    __shared__ unsigned long long skey[32];
    __shared__ float ssum[32];
    if (tid < 32) { skey[tid] = 0ull; ssum[tid] = 0.f; }

    const float* lrow = logits + (size_t)n * V;
    float* orow = out + (size_t)n * V;

    int   xt_pre = 0;
    float t_pre  = 0.f;
    if (tid == 0) { xt_pre = x_t[n]; t_pre = t_arr[0]; }

    for (int v = tid; v < V; v += nthreads)
        orow[v] = 0.f;

    unsigned long long key = 0ull;
    float psum = 0.f;
    for (int v = tid; v < V; v += nthreads) {
        float g = jax_gumbel_part((uint32_t)n * (uint32_t)V + (uint32_t)v);
        float score = lrow[v] + g;
        unsigned long long k =
            ((unsigned long long)float_mono(score) << 32) |
            (unsigned long long)(~(uint32_t)v);
        if (k > key) key = k;
        psum += source_p[v];
    }
#pragma unroll
    for (int s = 16; s > 0; s >>= 1) {
        unsigned long long ok = __shfl_down_sync(0xffffffffu, key, s);
        float os = __shfl_down_sync(0xffffffffu, psum, s);
        if (ok > key) key = ok;
        psum += os;
    }
    if (lane == 0) { skey[warp] = key; ssum[warp] = psum; }
    __syncthreads();

    if (warp == 0) {
        key  = skey[lane];
        psum = ssum[lane];
#pragma unroll
        for (int s = 16; s > 0; s >>= 1) {
            unsigned long long ok = __shfl_down_sync(0xffffffffu, key, s);
            float os = __shfl_down_sync(0xffffffffu, psum, s);
            if (ok > key) key = ok;
            psum += os;
        }
        if (lane == 0) {
            int x1 = (int)(~(uint32_t)(key & 0xffffffffull));
            write_sparse_pair(orow, source_p, x1, xt_pre, t_pre, psum);
        }
    }
}

extern "C" void kernel_launch(void* const* d_in, const int* in_sizes, int n_in,
                              void* d_out, int out_size) {
    // Bind inputs by element count (sizes distinct: N*V > V > N > 1).
    int li = 0, spi = 1, xti = 2, ti = 3;
    if (n_in == 4) {
        int order[4] = {0, 1, 2, 3};
        for (int a = 0; a < 4; a++)
            for (int b = a + 1; b < 4; b++)
                if (in_sizes[order[b]] > in_sizes[order[a]]) {
                    int tmp = order[a]; order[a] = order[b]; order[b] = tmp;
                }
        li  = order[0];   // N*V
        spi = order[1];   // V
        xti = order[2];   // N
        ti  = order[3];   // 1
    }

    const float* logits   = (const float*)d_in[li];
    const float* source_p = (const float*)d_in[spi];
    const int*   x_t      = (const int*)d_in[xti];
    const float* t_arr    = (const float*)d_in[ti];
    float* out = (float*)d_out;

    int total = in_sizes[li];     // N * V
    int V     = in_sizes[spi];    // vocab size
    int N     = total / V;        // tokens

    if (V == 1024) {
        // 2 CTAs (one cluster) per token, 512 threads each.
        ke_cluster_kernel<<<2 * N, 512>>>(logits, source_p, x_t, t_arr, out, V);
    } else {
        int threads = (V >= 1024) ? 1024 : ((V + 31) & ~31);
        if (threads < 32) threads = 32;
        kinetic_euler_mono<<<N, threads>>>(logits, source_p, x_t, t_arr, out, V);
    }
}